// round 2
// baseline (speedup 1.0000x reference)
#include <cuda_runtime.h>
#include <cuda_bf16.h>
#include <math.h>

#define N_NODES 100000
#define F_IN    128
#define F_H     16
#define F_OUT   3

// Scratch (no allocations allowed)
__device__ float g_deg [N_NODES];
__device__ float g_dinv[N_NODES];
__device__ float g_h1  [N_NODES * F_H];   // dinv[i] * (x[i] @ W1)
__device__ float g_out1[N_NODES * F_H];   // aggregated layer-1 pre-activation (no bias yet)
__device__ float g_h2  [N_NODES * F_OUT]; // dinv[i] * (relu(out1+b1) @ W2)
__device__ float g_out2[N_NODES * F_OUT];

// ---------------------------------------------------------------------------
// K0: deg = 1 (self loop)
__global__ void k_init_deg(int n) {
    int i = blockIdx.x * blockDim.x + threadIdx.x;
    if (i < n) g_deg[i] = 1.0f;
}

// K1: degree accumulate over dst
__global__ void k_degree(const int* __restrict__ dst, int E, int n) {
    int e = blockIdx.x * blockDim.x + threadIdx.x;
    if (e < E) {
        unsigned d = (unsigned)dst[e];
        if (d < (unsigned)n) atomicAdd(&g_deg[d], 1.0f);
    }
}

// K2: dinv = rsqrt(deg); h1 = dinv * (x @ W1); out1 = dinv * h1 (self-loop term)
__global__ __launch_bounds__(256) void k_gemm1(const float* __restrict__ x,
                                               const float* __restrict__ W1,
                                               int n) {
    __shared__ float sW[F_IN * F_H];  // 8 KB
    for (int t = threadIdx.x; t < F_IN * F_H; t += blockDim.x)
        sW[t] = W1[t];
    __syncthreads();

    int i = blockIdx.x * blockDim.x + threadIdx.x;
    if (i >= n) return;

    float acc[F_H];
#pragma unroll
    for (int f = 0; f < F_H; f++) acc[f] = 0.0f;

    const float4* xr = reinterpret_cast<const float4*>(x + (size_t)i * F_IN);
#pragma unroll 4
    for (int k4 = 0; k4 < F_IN / 4; k4++) {
        float4 v = __ldg(&xr[k4]);
        int k = k4 * 4;
#pragma unroll
        for (int f = 0; f < F_H; f++) {
            acc[f] += v.x * sW[(k + 0) * F_H + f];
            acc[f] += v.y * sW[(k + 1) * F_H + f];
            acc[f] += v.z * sW[(k + 2) * F_H + f];
            acc[f] += v.w * sW[(k + 3) * F_H + f];
        }
    }

    float di = rsqrtf(g_deg[i]);
    g_dinv[i] = di;

    float4* h1o  = reinterpret_cast<float4*>(g_h1  + (size_t)i * F_H);
    float4* o1o  = reinterpret_cast<float4*>(g_out1 + (size_t)i * F_H);
#pragma unroll
    for (int q = 0; q < F_H / 4; q++) {
        float4 h;
        h.x = di * acc[q * 4 + 0];
        h.y = di * acc[q * 4 + 1];
        h.z = di * acc[q * 4 + 2];
        h.w = di * acc[q * 4 + 3];
        h1o[q] = h;
        float4 o;  // self-loop contribution: dinv[i]*dinv[i]*(x@W1) = di * h
        o.x = di * h.x; o.y = di * h.y; o.z = di * h.z; o.w = di * h.w;
        o1o[q] = o;
    }
}

// K3: scatter layer 1: out1[d] += dinv[d] * h1[s]
__global__ __launch_bounds__(256) void k_scatter1(const int* __restrict__ src,
                                                  const int* __restrict__ dst,
                                                  int E, int n) {
    int e = blockIdx.x * blockDim.x + threadIdx.x;
    if (e >= E) return;
    unsigned s = (unsigned)src[e];
    unsigned d = (unsigned)dst[e];
    if (s >= (unsigned)n || d >= (unsigned)n) return;
    float dd = g_dinv[d];
    const float4* hs = reinterpret_cast<const float4*>(g_h1 + (size_t)s * F_H);
    float* od = g_out1 + (size_t)d * F_H;
#pragma unroll
    for (int q = 0; q < F_H / 4; q++) {
        float4 v = hs[q];
        atomicAdd(od + q * 4 + 0, dd * v.x);
        atomicAdd(od + q * 4 + 1, dd * v.y);
        atomicAdd(od + q * 4 + 2, dd * v.z);
        atomicAdd(od + q * 4 + 3, dd * v.w);
    }
}

// K4: v = relu(out1 + b1); h2 = dinv * (v @ W2); out2 = dinv * h2
__global__ __launch_bounds__(256) void k_gemm2(const float* __restrict__ b1,
                                               const float* __restrict__ W2,
                                               int n) {
    __shared__ float sW[F_H * F_OUT];
    __shared__ float sb[F_H];
    if (threadIdx.x < F_H * F_OUT) sW[threadIdx.x] = W2[threadIdx.x];
    if (threadIdx.x < F_H)         sb[threadIdx.x] = b1[threadIdx.x];
    __syncthreads();

    int i = blockIdx.x * blockDim.x + threadIdx.x;
    if (i >= n) return;

    const float4* o1 = reinterpret_cast<const float4*>(g_out1 + (size_t)i * F_H);
    float acc[F_OUT] = {0.0f, 0.0f, 0.0f};
#pragma unroll
    for (int q = 0; q < F_H / 4; q++) {
        float4 v4 = o1[q];
        float vv[4] = {v4.x, v4.y, v4.z, v4.w};
#pragma unroll
        for (int j = 0; j < 4; j++) {
            int k = q * 4 + j;
            float v = fmaxf(vv[j] + sb[k], 0.0f);
#pragma unroll
            for (int f = 0; f < F_OUT; f++)
                acc[f] += v * sW[k * F_OUT + f];
        }
    }

    float di = g_dinv[i];
#pragma unroll
    for (int f = 0; f < F_OUT; f++) {
        float h = di * acc[f];
        g_h2[(size_t)i * F_OUT + f]   = h;
        g_out2[(size_t)i * F_OUT + f] = di * h;  // self loop
    }
}

// K5: scatter layer 2
__global__ __launch_bounds__(256) void k_scatter2(const int* __restrict__ src,
                                                  const int* __restrict__ dst,
                                                  int E, int n) {
    int e = blockIdx.x * blockDim.x + threadIdx.x;
    if (e >= E) return;
    unsigned s = (unsigned)src[e];
    unsigned d = (unsigned)dst[e];
    if (s >= (unsigned)n || d >= (unsigned)n) return;
    float dd = g_dinv[d];
    const float* hs = g_h2 + (size_t)s * F_OUT;
    float* od = g_out2 + (size_t)d * F_OUT;
#pragma unroll
    for (int f = 0; f < F_OUT; f++)
        atomicAdd(od + f, dd * hs[f]);
}

// K6: z = out2 + b2; out = log_softmax(z)
__global__ __launch_bounds__(256) void k_final(const float* __restrict__ b2,
                                               float* __restrict__ out, int n) {
    int i = blockIdx.x * blockDim.x + threadIdx.x;
    if (i >= n) return;
    float z0 = g_out2[(size_t)i * 3 + 0] + b2[0];
    float z1 = g_out2[(size_t)i * 3 + 1] + b2[1];
    float z2 = g_out2[(size_t)i * 3 + 2] + b2[2];
    float m = fmaxf(z0, fmaxf(z1, z2));
    float lse = m + logf(expf(z0 - m) + expf(z1 - m) + expf(z2 - m));
    out[(size_t)i * 3 + 0] = z0 - lse;
    out[(size_t)i * 3 + 1] = z1 - lse;
    out[(size_t)i * 3 + 2] = z2 - lse;
}

extern "C" void kernel_launch(void* const* d_in, const int* in_sizes, int n_in,
                              void* d_out, int out_size) {
    const float* x  = (const float*)d_in[0];
    const int*   ei = (const int*)d_in[1];     // int64 in reference -> int32 on device
    const float* W1 = (const float*)d_in[2];
    const float* b1 = (const float*)d_in[3];
    const float* W2 = (const float*)d_in[4];
    const float* b2 = (const float*)d_in[5];
    float* out = (float*)d_out;

    const int n = in_sizes[0] / F_IN;          // 100000
    const int E = in_sizes[1] / 2;             // 1600000
    const int* src = ei;
    const int* dst = ei + E;

    const int TB = 256;
    const int gn = (n + TB - 1) / TB;
    const int ge = (E + TB - 1) / TB;

    k_init_deg<<<gn, TB>>>(n);
    k_degree  <<<ge, TB>>>(dst, E, n);
    k_gemm1   <<<gn, TB>>>(x, W1, n);
    k_scatter1<<<ge, TB>>>(src, dst, E, n);
    k_gemm2   <<<gn, TB>>>(b1, W2, n);
    k_scatter2<<<ge, TB>>>(src, dst, E, n);
    k_final   <<<gn, TB>>>(b2, out, n);
}